// round 1
// baseline (speedup 1.0000x reference)
#include <cuda_runtime.h>
#include <math.h>

#define NN 50000
#define DD 128
#define EE 600000
#define ND ((size_t)NN * DD)

// Scratch (no cudaMalloc allowed): ~31 MB of device globals.
__device__ __align__(16) float g_aggr[NN * DD];
__device__ float g_s[NN];
__device__ float g_t[NN];
__device__ int g_src[EE];
__device__ int g_dst[EE];
__device__ int g_is64;

__device__ __forceinline__ float warp_sum(float v) {
#pragma unroll
    for (int o = 16; o > 0; o >>= 1) v += __shfl_xor_sync(0xffffffffu, v, o);
    return v;
}

// ---------------------------------------------------------------------------
// edge_index dtype detection: if the buffer is int64 (little-endian, values in
// [0, 50000)), every odd int32 slot is 0. 64 consecutive odd slots all zero is
// astronomically unlikely for an int32 buffer of random values in [0, 50000).
// Reading 129 int32 slots is in-bounds for both dtypes (buffer >= 2.4M int32).
__global__ void detect_kernel(const int* __restrict__ ei32) {
    int all0 = 1;
#pragma unroll
    for (int i = 1; i < 129; i += 2) all0 &= (ei32[i] == 0);
    g_is64 = all0;
}

__global__ void convert_kernel(const void* __restrict__ ei) {
    int e = blockIdx.x * blockDim.x + threadIdx.x;
    if (e >= EE) return;
    if (g_is64) {
        const long long* p = (const long long*)ei;
        g_src[e] = (int)p[e];
        g_dst[e] = (int)p[EE + e];
    } else {
        const int* p = (const int*)ei;
        g_src[e] = p[e];
        g_dst[e] = p[EE + e];
    }
}

// ---------------------------------------------------------------------------
// Warp-per-row L2 normalize of x -> out[0]; also zero g_aggr row and compute
// s/t projections for hop 0.
__global__ void norm_x_kernel(const float* __restrict__ x,
                              const float* __restrict__ w0,
                              float* __restrict__ out) {
    int row = (blockIdx.x * blockDim.x + threadIdx.x) >> 5;
    int lane = threadIdx.x & 31;
    if (row >= NN) return;

    float4 v = ((const float4*)(x + (size_t)row * DD))[lane];
    ((float4*)(g_aggr + (size_t)row * DD))[lane] = make_float4(0.f, 0.f, 0.f, 0.f);

    float ss = v.x * v.x + v.y * v.y + v.z * v.z + v.w * v.w;
    ss = warp_sum(ss);
    float inv = 1.0f / fmaxf(sqrtf(ss), 1e-12f);

    float4 o = make_float4(v.x * inv, v.y * inv, v.z * inv, v.w * inv);
    ((float4*)(out + (size_t)row * DD))[lane] = o;

    float4 a = ((const float4*)w0)[lane];
    float4 b = ((const float4*)(w0 + DD))[lane];
    float sd = o.x * a.x + o.y * a.y + o.z * a.z + o.w * a.w;
    float td = o.x * b.x + o.y * b.y + o.z * b.z + o.w * b.w;
    sd = warp_sum(sd);
    td = warp_sum(td);
    if (lane == 0) { g_s[row] = sd; g_t[row] = td; }
}

// ---------------------------------------------------------------------------
// Warp-per-edge: gate alpha = sigmoid(selu(s[src] + t[dst] + b)), then
// aggr[dst] += alpha * h[src] via f32 RED (atomicAdd, no return value used).
__global__ void edge_kernel(const float* __restrict__ h,
                            const float* __restrict__ bptr) {
    int e = (blockIdx.x * blockDim.x + threadIdx.x) >> 5;
    int lane = threadIdx.x & 31;
    if (e >= EE) return;

    int src = g_src[e];
    int dst = g_dst[e];

    float ev = g_s[src] + g_t[dst] + *bptr;
    const float SC = 1.0507009873554804934193349852946f;
    const float AL = 1.6732632423543772848170429916717f;
    float selu = ev > 0.f ? SC * ev : SC * AL * expm1f(ev);
    float alpha = 1.0f / (1.0f + expf(-selu));

    float4 v = ((const float4*)(h + (size_t)src * DD))[lane];
    float* ag = g_aggr + (size_t)dst * DD + lane * 4;
    atomicAdd(ag + 0, alpha * v.x);
    atomicAdd(ag + 1, alpha * v.y);
    atomicAdd(ag + 2, alpha * v.z);
    atomicAdd(ag + 3, alpha * v.w);
}

// ---------------------------------------------------------------------------
// Warp-per-row: val = aggr + 0.1*noise; zero aggr for next hop (ZERO_AGGR);
// L2-normalize into out; optionally project s/t with next hop's weights.
template <bool COMPUTE_ST, bool ZERO_AGGR>
__global__ void norm_hop_kernel(const float* __restrict__ noise_k,
                                const float* __restrict__ wk,
                                float* __restrict__ out) {
    int row = (blockIdx.x * blockDim.x + threadIdx.x) >> 5;
    int lane = threadIdx.x & 31;
    if (row >= NN) return;

    float4 v = ((const float4*)(g_aggr + (size_t)row * DD))[lane];
    float4 n = ((const float4*)(noise_k + (size_t)row * DD))[lane];
    v.x += 0.1f * n.x; v.y += 0.1f * n.y; v.z += 0.1f * n.z; v.w += 0.1f * n.w;

    if (ZERO_AGGR)
        ((float4*)(g_aggr + (size_t)row * DD))[lane] = make_float4(0.f, 0.f, 0.f, 0.f);

    float ss = v.x * v.x + v.y * v.y + v.z * v.z + v.w * v.w;
    ss = warp_sum(ss);
    float inv = 1.0f / fmaxf(sqrtf(ss), 1e-12f);

    float4 o = make_float4(v.x * inv, v.y * inv, v.z * inv, v.w * inv);
    ((float4*)(out + (size_t)row * DD))[lane] = o;

    if (COMPUTE_ST) {
        float4 a = ((const float4*)wk)[lane];
        float4 b = ((const float4*)(wk + DD))[lane];
        float sd = o.x * a.x + o.y * a.y + o.z * a.z + o.w * a.w;
        float td = o.x * b.x + o.y * b.y + o.z * b.z + o.w * b.w;
        sd = warp_sum(sd);
        td = warp_sum(td);
        if (lane == 0) { g_s[row] = sd; g_t[row] = td; }
    }
}

// ---------------------------------------------------------------------------
extern "C" void kernel_launch(void* const* d_in, const int* in_sizes, int n_in,
                              void* d_out, int out_size) {
    const float* x = (const float*)d_in[0];
    const void* ei = d_in[1];
    const float* attn_w = (const float*)d_in[2];
    const float* attn_b = (const float*)d_in[3];
    const float* noise = (const float*)d_in[4];
    float* out = (float*)d_out;

    const int NORM_GRID = (NN + 7) / 8;      // 8 warps / 256-thread block
    const int EDGE_GRID = (EE + 7) / 8;      // warp per edge

    detect_kernel<<<1, 1>>>((const int*)ei);
    convert_kernel<<<(EE + 255) / 256, 256>>>(ei);

    // out[0] = l2norm(x); zero aggr; s/t for hop 0
    norm_x_kernel<<<NORM_GRID, 256>>>(x, attn_w, out);

    // hop 0
    edge_kernel<<<EDGE_GRID, 256>>>(out, attn_b + 0);
    norm_hop_kernel<true, true><<<NORM_GRID, 256>>>(noise, attn_w + 2 * DD, out + ND);

    // hop 1
    edge_kernel<<<EDGE_GRID, 256>>>(out + ND, attn_b + 1);
    norm_hop_kernel<true, true><<<NORM_GRID, 256>>>(noise + ND, attn_w + 4 * DD, out + 2 * ND);

    // hop 2 (no next-hop projections, no need to re-zero aggr)
    edge_kernel<<<EDGE_GRID, 256>>>(out + 2 * ND, attn_b + 2);
    norm_hop_kernel<false, false><<<NORM_GRID, 256>>>(noise + 2 * ND, attn_w, out + 3 * ND);
}

// round 2
// speedup vs baseline: 2.2316x; 2.2316x over previous
#include <cuda_runtime.h>
#include <math.h>

#define NN 50000
#define DD 128
#define EE 600000
#define ND ((size_t)NN * DD)

// Scratch (no cudaMalloc allowed): device globals.
__device__ float g_s[2][NN];        // gate projections, double-buffered by hop parity
__device__ float g_t[2][NN];
__device__ int g_src[EE];
__device__ int g_dst[EE];
__device__ int g_cnt[NN];           // in-degree counts (doubles as fill cursor)
__device__ int g_off[NN + 1];       // CSR offsets
__device__ int g_csr_eid[EE];       // edge ids grouped by dst (sorted within bucket)
__device__ int g_csr_src[EE];       // src node per CSR slot
__device__ int g_is64;

__device__ __forceinline__ float warp_sum(float v) {
#pragma unroll
    for (int o = 16; o > 0; o >>= 1) v += __shfl_xor_sync(0xffffffffu, v, o);
    return v;
}

// ---------------------------------------------------------------------------
// edge_index dtype detection: int64 little-endian with values < 50000 means
// every odd int32 slot is zero. 64 consecutive zero odd-slots ~ impossible for
// a random int32 buffer.
__global__ void detect_kernel(const int* __restrict__ ei32) {
    int all0 = 1;
#pragma unroll
    for (int i = 1; i < 129; i += 2) all0 &= (ei32[i] == 0);
    g_is64 = all0;
}

__global__ void zero_kernel() {
    int i = blockIdx.x * blockDim.x + threadIdx.x;
    if (i < NN) g_cnt[i] = 0;
}

// Unpack edge index to int32 src/dst and histogram dst.
__global__ void convert_kernel(const void* __restrict__ ei) {
    int e = blockIdx.x * blockDim.x + threadIdx.x;
    if (e >= EE) return;
    int s, d;
    if (g_is64) {
        const long long* p = (const long long*)ei;
        s = (int)p[e];
        d = (int)p[EE + e];
    } else {
        const int* p = (const int*)ei;
        s = p[e];
        d = p[EE + e];
    }
    g_src[e] = s;
    g_dst[e] = d;
    atomicAdd(&g_cnt[d], 1);
}

// Single-block exclusive scan of g_cnt -> g_off (NN=50000, 49 chunks of 1024).
__global__ void scan_kernel() {
    __shared__ int sh[1024];
    __shared__ int carry;
    if (threadIdx.x == 0) carry = 0;
    __syncthreads();
    for (int base = 0; base < NN; base += 1024) {
        int i = base + (int)threadIdx.x;
        int v = (i < NN) ? g_cnt[i] : 0;
        sh[threadIdx.x] = v;
        __syncthreads();
#pragma unroll
        for (int o = 1; o < 1024; o <<= 1) {
            int t = (threadIdx.x >= o) ? sh[threadIdx.x - o] : 0;
            __syncthreads();
            sh[threadIdx.x] += t;
            __syncthreads();
        }
        if (i < NN) g_off[i] = carry + sh[threadIdx.x] - v;
        __syncthreads();
        if (threadIdx.x == 1023) carry += sh[1023];
        __syncthreads();
    }
    if (threadIdx.x == 0) g_off[NN] = EE;
}

// Scatter edge ids into CSR buckets (g_cnt reused as fill cursor, re-zeroed
// implicitly by consuming it: reset here with atomicSub trick is messy, so
// zero again first via zero2).
__global__ void zero2_kernel() {
    int i = blockIdx.x * blockDim.x + threadIdx.x;
    if (i < NN) g_cnt[i] = 0;
}

__global__ void scatter_kernel() {
    int e = blockIdx.x * blockDim.x + threadIdx.x;
    if (e >= EE) return;
    int d = g_dst[e];
    int pos = g_off[d] + atomicAdd(&g_cnt[d], 1);
    g_csr_eid[pos] = e;
}

// Deterministic order: insertion-sort each bucket by edge id, then materialize
// the src node per slot.
__global__ void sort_fill_kernel() {
    int d = blockIdx.x * blockDim.x + threadIdx.x;
    if (d >= NN) return;
    int beg = g_off[d], end = g_off[d + 1];
    for (int i = beg + 1; i < end; i++) {
        int key = g_csr_eid[i];
        int j = i - 1;
        while (j >= beg && g_csr_eid[j] > key) {
            g_csr_eid[j + 1] = g_csr_eid[j];
            j--;
        }
        g_csr_eid[j + 1] = key;
    }
    for (int i = beg; i < end; i++) g_csr_src[i] = g_src[g_csr_eid[i]];
}

// ---------------------------------------------------------------------------
// out[0] = l2norm(x); compute s/t (parity 0) for hop 0. Warp per row.
__global__ void norm_x_kernel(const float* __restrict__ x,
                              const float* __restrict__ w0,
                              float* __restrict__ out) {
    int row = (blockIdx.x * blockDim.x + threadIdx.x) >> 5;
    int lane = threadIdx.x & 31;
    if (row >= NN) return;

    float4 v = ((const float4*)(x + (size_t)row * DD))[lane];
    float ss = v.x * v.x + v.y * v.y + v.z * v.z + v.w * v.w;
    ss = warp_sum(ss);
    float inv = 1.0f / fmaxf(sqrtf(ss), 1e-12f);

    float4 o = make_float4(v.x * inv, v.y * inv, v.z * inv, v.w * inv);
    ((float4*)(out + (size_t)row * DD))[lane] = o;

    float4 a = ((const float4*)w0)[lane];
    float4 b = ((const float4*)(w0 + DD))[lane];
    float sd = o.x * a.x + o.y * a.y + o.z * a.z + o.w * a.w;
    float td = o.x * b.x + o.y * b.y + o.z * b.z + o.w * b.w;
    sd = warp_sum(sd);
    td = warp_sum(td);
    if (lane == 0) { g_s[0][row] = sd; g_t[0][row] = td; }
}

// ---------------------------------------------------------------------------
// Fused hop: warp per dst row. Register-accumulate alpha*h[src] over the CSR
// bucket (no atomics), add noise, L2-normalize, write out, and (optionally)
// project s/t for the next hop into the other parity buffer.
template <bool COMPUTE_ST>
__global__ void hop_kernel(const float* __restrict__ h,
                           const float* __restrict__ bptr,
                           const float* __restrict__ noise_k,
                           const float* __restrict__ wk,
                           float* __restrict__ out,
                           int parity) {
    int row = (blockIdx.x * blockDim.x + threadIdx.x) >> 5;
    int lane = threadIdx.x & 31;
    if (row >= NN) return;

    const float* sbuf = g_s[parity];
    float tb = g_t[parity][row] + *bptr;

    int beg = g_off[row], end = g_off[row + 1];
    float4 acc = make_float4(0.f, 0.f, 0.f, 0.f);

    const float SC = 1.0507009873554804934193349852946f;
    const float AL = 1.6732632423543772848170429916717f;

    int i = beg;
    // 2-wide software pipeline for ILP on the dependent load chains.
    for (; i + 1 < end; i += 2) {
        int s0 = g_csr_src[i];
        int s1 = g_csr_src[i + 1];
        float e0 = sbuf[s0] + tb;
        float e1 = sbuf[s1] + tb;
        float4 v0 = ((const float4*)(h + (size_t)s0 * DD))[lane];
        float4 v1 = ((const float4*)(h + (size_t)s1 * DD))[lane];
        float u0 = e0 > 0.f ? SC * e0 : SC * AL * expm1f(e0);
        float u1 = e1 > 0.f ? SC * e1 : SC * AL * expm1f(e1);
        float a0 = 1.0f / (1.0f + expf(-u0));
        float a1 = 1.0f / (1.0f + expf(-u1));
        acc.x += a0 * v0.x + a1 * v1.x;
        acc.y += a0 * v0.y + a1 * v1.y;
        acc.z += a0 * v0.z + a1 * v1.z;
        acc.w += a0 * v0.w + a1 * v1.w;
    }
    if (i < end) {
        int s0 = g_csr_src[i];
        float e0 = sbuf[s0] + tb;
        float4 v0 = ((const float4*)(h + (size_t)s0 * DD))[lane];
        float u0 = e0 > 0.f ? SC * e0 : SC * AL * expm1f(e0);
        float a0 = 1.0f / (1.0f + expf(-u0));
        acc.x += a0 * v0.x; acc.y += a0 * v0.y;
        acc.z += a0 * v0.z; acc.w += a0 * v0.w;
    }

    float4 n = ((const float4*)(noise_k + (size_t)row * DD))[lane];
    acc.x += 0.1f * n.x; acc.y += 0.1f * n.y;
    acc.z += 0.1f * n.z; acc.w += 0.1f * n.w;

    float ss = acc.x * acc.x + acc.y * acc.y + acc.z * acc.z + acc.w * acc.w;
    ss = warp_sum(ss);
    float inv = 1.0f / fmaxf(sqrtf(ss), 1e-12f);

    float4 o = make_float4(acc.x * inv, acc.y * inv, acc.z * inv, acc.w * inv);
    ((float4*)(out + (size_t)row * DD))[lane] = o;

    if (COMPUTE_ST) {
        float4 a = ((const float4*)wk)[lane];
        float4 b = ((const float4*)(wk + DD))[lane];
        float sd = o.x * a.x + o.y * a.y + o.z * a.z + o.w * a.w;
        float td = o.x * b.x + o.y * b.y + o.z * b.z + o.w * b.w;
        sd = warp_sum(sd);
        td = warp_sum(td);
        int np = parity ^ 1;
        if (lane == 0) { g_s[np][row] = sd; g_t[np][row] = td; }
    }
}

// ---------------------------------------------------------------------------
extern "C" void kernel_launch(void* const* d_in, const int* in_sizes, int n_in,
                              void* d_out, int out_size) {
    const float* x = (const float*)d_in[0];
    const void* ei = d_in[1];
    const float* attn_w = (const float*)d_in[2];
    const float* attn_b = (const float*)d_in[3];
    const float* noise = (const float*)d_in[4];
    float* out = (float*)d_out;

    const int NORM_GRID = (NN + 7) / 8;   // warp per row, 256-thread blocks
    const int E256 = (EE + 255) / 256;
    const int N256 = (NN + 255) / 256;

    // CSR build (per replay; deterministic via bucket sort)
    detect_kernel<<<1, 1>>>((const int*)ei);
    zero_kernel<<<N256, 256>>>();
    convert_kernel<<<E256, 256>>>(ei);
    scan_kernel<<<1, 1024>>>();
    zero2_kernel<<<N256, 256>>>();
    scatter_kernel<<<E256, 256>>>();
    sort_fill_kernel<<<N256, 256>>>();

    // out[0] = l2norm(x); s/t parity 0
    norm_x_kernel<<<NORM_GRID, 256>>>(x, attn_w, out);

    // hops
    hop_kernel<true><<<NORM_GRID, 256>>>(out, attn_b + 0, noise,
                                         attn_w + 2 * DD, out + ND, 0);
    hop_kernel<true><<<NORM_GRID, 256>>>(out + ND, attn_b + 1, noise + ND,
                                         attn_w + 4 * DD, out + 2 * ND, 1);
    hop_kernel<false><<<NORM_GRID, 256>>>(out + 2 * ND, attn_b + 2, noise + 2 * ND,
                                          attn_w, out + 3 * ND, 0);
}